// round 1
// baseline (speedup 1.0000x reference)
#include <cuda_runtime.h>
#include <math.h>

// ---------------- problem constants ----------------
#define N_PIX  16384          // 128*128 spatial
#define BATCH  8
#define CDIM   256
#define INNER  512            // HEADS*DIM_HEAD
#define NHEADS 8
#define DHEAD  64

// ---------------- scratch (static device globals; no allocation) ----------------
__device__ __align__(16) float g_dw  [(size_t)BATCH * CDIM  * N_PIX];   // depthwise conv out
__device__ __align__(16) float g_q   [(size_t)BATCH * INNER * N_PIX];   // q (then softmaxed)
__device__ __align__(16) float g_kv  [(size_t)BATCH * 2*INNER * N_PIX]; // k (ch 0..511), v (512..1023)
__device__ __align__(16) float g_av  [(size_t)BATCH * INNER * N_PIX];   // gelu(q@ctx)
__device__ __align__(16) float g_part[64 * 8 * 64 * 64];                // split-K context partials
__device__ __align__(16) float g_ctx [64 * 64 * 64];                    // per-(b,h) ctx^T  [e][d]

__device__ __forceinline__ float gelu_exact(float x) { return x * normcdff(x); }

// ---------------- depthwise 3x3, pad 1 ----------------
__global__ void __launch_bounds__(256) k_dwconv(const float* __restrict__ in,
                                                const float* __restrict__ wdw)
{
    int plane = blockIdx.y;              // b*256 + c
    int c     = plane & 255;
    const float* ip = in   + (size_t)plane * N_PIX;
    float*       op = g_dw + (size_t)plane * N_PIX;

    float w[9];
#pragma unroll
    for (int k = 0; k < 9; ++k) w[k] = __ldg(wdw + c * 9 + k);

    int p = blockIdx.x * 256 + threadIdx.x;      // 0..16383
    int y = p >> 7, x = p & 127;
    float s = 0.f;
#pragma unroll
    for (int dy = -1; dy <= 1; ++dy) {
        int yy = y + dy;
        if (yy < 0 || yy > 127) continue;
#pragma unroll
        for (int dx = -1; dx <= 1; ++dx) {
            int xx = x + dx;
            if (xx < 0 || xx > 127) continue;
            s += ip[yy * 128 + xx] * w[(dy + 1) * 3 + (dx + 1)];
        }
    }
    op[p] = s;
}

// ---------------- generic channel-major GEMM ----------------
// Y[o, p] = sum_c W[o, c] * X[c, p]     (X rows contiguous in p; W row-major [O, C])
// Batched over blockIdx.z with element strides xs/ws/ys. Optional GELU on output, bias add.
// Block: 128 pixels x BN outs, BK=8, 256 threads, per-thread 8 x (BN/16).
template <int BN, bool GELU_OUT, bool BIAS>
__global__ void __launch_bounds__(256) k_gemm(
    const float* __restrict__ X, const float* __restrict__ W,
    const float* __restrict__ bias, float* __restrict__ Y,
    int C, int N, long long xs, long long ws, long long ys)
{
    constexpr int BM = 128, BK = 8;
    constexpr int TN = BN / 16;          // 8 or 4

    __shared__ __align__(16) float Xs[BK][BM];
    __shared__ __align__(16) float Ws[BK][BN];

    const float* Xb = X + (long long)blockIdx.z * xs;
    const float* Wb = W + (long long)blockIdx.z * ws;
    float*       Yb = Y + (long long)blockIdx.z * ys;

    const int p0 = blockIdx.x * BM;
    const int o0 = blockIdx.y * BN;
    const int t  = threadIdx.x;
    const int tm = t & 15;               // pixel group
    const int tn = t >> 4;               // output group

    float acc[8][TN];
#pragma unroll
    for (int i = 0; i < 8; ++i)
#pragma unroll
        for (int j = 0; j < TN; ++j) acc[i][j] = 0.f;

    for (int c0 = 0; c0 < C; c0 += BK) {
        // --- load X tile: BK x BM  (exactly 256 float4) ---
        {
            int kk = t >> 5, p4 = t & 31;
            float4 xv = *(const float4*)(Xb + (size_t)(c0 + kk) * N + p0 + p4 * 4);
            *(float4*)&Xs[kk][p4 * 4] = xv;
        }
        // --- load W tile: BN x BK, transposed to Ws[k][o] ---
        for (int i = t; i < BN * BK / 4; i += 256) {
            int o = i >> 1, cq = i & 1;  // BK/4 == 2
            float4 wv = *(const float4*)(Wb + (size_t)(o0 + o) * C + c0 + cq * 4);
            Ws[cq * 4 + 0][o] = wv.x;
            Ws[cq * 4 + 1][o] = wv.y;
            Ws[cq * 4 + 2][o] = wv.z;
            Ws[cq * 4 + 3][o] = wv.w;
        }
        __syncthreads();

#pragma unroll
        for (int kk = 0; kk < BK; ++kk) {
            float a[8], b[TN];
#pragma unroll
            for (int cm = 0; cm < 2; ++cm) {
                float4 av = *(const float4*)&Xs[kk][tm * 4 + cm * 64];
                a[cm * 4 + 0] = av.x; a[cm * 4 + 1] = av.y;
                a[cm * 4 + 2] = av.z; a[cm * 4 + 3] = av.w;
            }
#pragma unroll
            for (int cn = 0; cn < TN / 4; ++cn) {
                float4 bv = *(const float4*)&Ws[kk][tn * 4 + cn * 64];
                b[cn * 4 + 0] = bv.x; b[cn * 4 + 1] = bv.y;
                b[cn * 4 + 2] = bv.z; b[cn * 4 + 3] = bv.w;
            }
#pragma unroll
            for (int i = 0; i < 8; ++i)
#pragma unroll
                for (int j = 0; j < TN; ++j)
                    acc[i][j] += a[i] * b[j];
        }
        __syncthreads();
    }

    // --- epilogue ---
#pragma unroll
    for (int cn = 0; cn < TN / 4; ++cn) {
#pragma unroll
        for (int j = 0; j < 4; ++j) {
            int o = o0 + tn * 4 + cn * 64 + j;
            float bb = 0.f;
            if (BIAS) bb = __ldg(&bias[o]);
#pragma unroll
            for (int cm = 0; cm < 2; ++cm) {
                float4 v;
                v.x = acc[cm * 4 + 0][cn * 4 + j] + bb;
                v.y = acc[cm * 4 + 1][cn * 4 + j] + bb;
                v.z = acc[cm * 4 + 2][cn * 4 + j] + bb;
                v.w = acc[cm * 4 + 3][cn * 4 + j] + bb;
                if (GELU_OUT) {
                    v.x = gelu_exact(v.x); v.y = gelu_exact(v.y);
                    v.z = gelu_exact(v.z); v.w = gelu_exact(v.w);
                }
                *(float4*)(Yb + (size_t)o * N + p0 + tm * 4 + cm * 64) = v;
            }
        }
    }
}

// ---------------- softmax over feature dim d (64) for q, then * scale ----------------
// q layout [B][512][N]; group = channels h*64 .. h*64+63 at fixed (b, n)
__global__ void __launch_bounds__(256) k_softmax_q(float* __restrict__ q)
{
    int idx = blockIdx.x * 256 + threadIdx.x;      // 8*8*16384 items
    int n   = idx & (N_PIX - 1);
    int bh  = idx >> 14;
    int b   = bh >> 3, h = bh & 7;
    float* base = q + ((size_t)b * INNER + (size_t)h * 64) * N_PIX + n;

    float v[64];
    float m = -3.4e38f;
#pragma unroll
    for (int d = 0; d < 64; ++d) {
        v[d] = base[(size_t)d * N_PIX];
        m = fmaxf(m, v[d]);
    }
    float s = 0.f;
#pragma unroll
    for (int d = 0; d < 64; ++d) { v[d] = expf(v[d] - m); s += v[d]; }
    float inv = 0.125f / s;                        // scale = DHEAD^-0.5 = 1/8
#pragma unroll
    for (int d = 0; d < 64; ++d) base[(size_t)d * N_PIX] = v[d] * inv;
}

// ---------------- softmax over spatial dim N (16384) for k ----------------
// k rows: kv channels 0..511 per batch; one block per row.
__global__ void __launch_bounds__(256) k_softmax_k(float* __restrict__ kv)
{
    int row = blockIdx.x;                 // 0..4095
    int b = row >> 9, ch = row & 511;
    float* base = kv + ((size_t)b * 1024 + ch) * N_PIX;
    float4* b4 = (float4*)base;
    int t = threadIdx.x;
    int lane = t & 31, warp = t >> 5;

    __shared__ float red[40];

    float4 r[16];
    float m = -3.4e38f;
#pragma unroll
    for (int i = 0; i < 16; ++i) {
        r[i] = b4[t + i * 256];
        m = fmaxf(m, fmaxf(fmaxf(r[i].x, r[i].y), fmaxf(r[i].z, r[i].w)));
    }
#pragma unroll
    for (int o = 16; o; o >>= 1) m = fmaxf(m, __shfl_xor_sync(0xffffffffu, m, o));
    if (lane == 0) red[warp] = m;
    __syncthreads();
    if (t == 0) {
        float mm = red[0];
        for (int w = 1; w < 8; ++w) mm = fmaxf(mm, red[w]);
        red[32] = mm;
    }
    __syncthreads();
    m = red[32];

    float s = 0.f;
#pragma unroll
    for (int i = 0; i < 16; ++i) {
        r[i].x = expf(r[i].x - m);
        r[i].y = expf(r[i].y - m);
        r[i].z = expf(r[i].z - m);
        r[i].w = expf(r[i].w - m);
        s += r[i].x + r[i].y + r[i].z + r[i].w;
    }
#pragma unroll
    for (int o = 16; o; o >>= 1) s += __shfl_xor_sync(0xffffffffu, s, o);
    if (lane == 0) red[warp] = s;
    __syncthreads();
    if (t == 0) {
        float tt = 0.f;
        for (int w = 0; w < 8; ++w) tt += red[w];
        red[33] = tt;
    }
    __syncthreads();
    float inv = 1.0f / red[33];
#pragma unroll
    for (int i = 0; i < 16; ++i) {
        r[i].x *= inv; r[i].y *= inv; r[i].z *= inv; r[i].w *= inv;
        b4[t + i * 256] = r[i];
    }
}

// ---------------- context partials: P[bh][s][e][d] = sum_{n in slab s} v[e][n]*k[d][n] ----------------
__global__ void __launch_bounds__(256) k_ctx(const float* __restrict__ kv,
                                             float* __restrict__ part)
{
    __shared__ __align__(16) float ks[32][68];   // [nn][d], padded
    __shared__ __align__(16) float vs[32][68];

    int bh = blockIdx.x >> 3;
    int s  = blockIdx.x & 7;
    int b  = bh >> 3, h = bh & 7;
    const float* kb = kv + ((size_t)b * 1024 + (size_t)h * 64) * N_PIX;
    const float* vb = kv + ((size_t)b * 1024 + 512 + (size_t)h * 64) * N_PIX;

    int t  = threadIdx.x;
    int d0 = (t & 15) * 4;
    int e0 = (t >> 4) * 4;

    float acc[4][4];
#pragma unroll
    for (int j = 0; j < 4; ++j)
#pragma unroll
        for (int i = 0; i < 4; ++i) acc[j][i] = 0.f;

    int nbase = s * 2048;
    for (int nc = 0; nc < 2048; nc += 32) {
        int n0 = nbase + nc;
        __syncthreads();
#pragma unroll
        for (int rep = 0; rep < 2; ++rep) {
            int f   = t + rep * 256;
            int row = f >> 3;            // channel index 0..63
            int c4  = (f & 7) * 4;       // nn base
            float4 kk4 = *(const float4*)(kb + (size_t)row * N_PIX + n0 + c4);
            ks[c4 + 0][row] = kk4.x; ks[c4 + 1][row] = kk4.y;
            ks[c4 + 2][row] = kk4.z; ks[c4 + 3][row] = kk4.w;
            float4 vv4 = *(const float4*)(vb + (size_t)row * N_PIX + n0 + c4);
            vs[c4 + 0][row] = vv4.x; vs[c4 + 1][row] = vv4.y;
            vs[c4 + 2][row] = vv4.z; vs[c4 + 3][row] = vv4.w;
        }
        __syncthreads();
#pragma unroll
        for (int nn = 0; nn < 32; ++nn) {
            float4 kr = *(const float4*)&ks[nn][d0];
            float4 vr = *(const float4*)&vs[nn][e0];
            acc[0][0] += vr.x * kr.x; acc[0][1] += vr.x * kr.y; acc[0][2] += vr.x * kr.z; acc[0][3] += vr.x * kr.w;
            acc[1][0] += vr.y * kr.x; acc[1][1] += vr.y * kr.y; acc[1][2] += vr.y * kr.z; acc[1][3] += vr.y * kr.w;
            acc[2][0] += vr.z * kr.x; acc[2][1] += vr.z * kr.y; acc[2][2] += vr.z * kr.z; acc[2][3] += vr.z * kr.w;
            acc[3][0] += vr.w * kr.x; acc[3][1] += vr.w * kr.y; acc[3][2] += vr.w * kr.z; acc[3][3] += vr.w * kr.w;
        }
    }

    size_t obase = ((size_t)blockIdx.x * 64 + e0) * 64 + d0;
#pragma unroll
    for (int j = 0; j < 4; ++j) {
        float4 o4 = make_float4(acc[j][0], acc[j][1], acc[j][2], acc[j][3]);
        *(float4*)&part[obase + (size_t)j * 64] = o4;
    }
}

// ---------------- reduce context partials: ctx^T[bh][e][d] ----------------
__global__ void k_ctx_reduce(const float* __restrict__ part, float* __restrict__ ctx)
{
    int i  = blockIdx.x * 256 + threadIdx.x;   // < 262144
    int bh = i >> 12;
    int ed = i & 4095;
    float s = 0.f;
#pragma unroll
    for (int ss = 0; ss < 8; ++ss)
        s += part[((size_t)bh * 8 + ss) * 4096 + ed];
    ctx[i] = s;
}

// ---------------- launch ----------------
extern "C" void kernel_launch(void* const* d_in, const int* in_sizes, int n_in,
                              void* d_out, int out_size)
{
    const float* fmap  = (const float*)d_in[0];
    const float* w_q   = (const float*)d_in[1];
    const float* w_dw  = (const float*)d_in[2];
    const float* w_pw  = (const float*)d_in[3];
    const float* w_out = (const float*)d_in[4];
    const float* b_out = (const float*)d_in[5];
    float* out = (float*)d_out;

    float *dw, *q, *kvp, *av, *part, *ctx;
    cudaGetSymbolAddress((void**)&dw,   g_dw);
    cudaGetSymbolAddress((void**)&q,    g_q);
    cudaGetSymbolAddress((void**)&kvp,  g_kv);
    cudaGetSymbolAddress((void**)&av,   g_av);
    cudaGetSymbolAddress((void**)&part, g_part);
    cudaGetSymbolAddress((void**)&ctx,  g_ctx);

    // 1) depthwise 3x3
    k_dwconv<<<dim3(64, BATCH * CDIM), 256>>>(fmap, w_dw);

    // 2) q = w_q @ fmap        [b][512][N]
    k_gemm<128, false, false><<<dim3(128, 4, 8), 256>>>(
        fmap, w_q, nullptr, q, 256, N_PIX, 256LL * N_PIX, 0, 512LL * N_PIX);

    // 3) kv = w_pw @ dw        [b][1024][N]
    k_gemm<128, false, false><<<dim3(128, 8, 8), 256>>>(
        dw, w_pw, nullptr, kvp, 256, N_PIX, 256LL * N_PIX, 0, 1024LL * N_PIX);

    // 4) softmax over d for q (in place) * 1/8
    k_softmax_q<<<4096, 256>>>(q);

    // 5) softmax over N for k (in place, channels 0..511 of kv)
    k_softmax_k<<<4096, 256>>>(kvp);

    // 6) context split-K partials + reduce -> ctx^T[e][d] per (b,h)
    k_ctx<<<512, 256>>>(kvp, part);
    k_ctx_reduce<<<1024, 256>>>(part, ctx);

    // 7) av = gelu(ctx^T @ q)  batched over 64 (b,h) pairs   [b][512][N]
    k_gemm<64, true, false><<<dim3(128, 1, 64), 256>>>(
        q, ctx, nullptr, av, 64, N_PIX, 64LL * N_PIX, 4096LL, 64LL * N_PIX);

    // 8) out = w_out @ av + b_out   [b][256][N]
    k_gemm<128, false, true><<<dim3(128, 2, 8), 256>>>(
        av, w_out, b_out, out, 512, N_PIX, 512LL * N_PIX, 0, 256LL * N_PIX);
}